// round 11
// baseline (speedup 1.0000x reference)
#include <cuda_runtime.h>
#include <cuda_fp16.h>
#include <math.h>

// ---------------------------------------------------------------------------
// ControllerLSTM on GB300, round 9.
// Diagnosis: rounds 5-8 were bound by ~131K F2F converts + 262K FFMA per SM
// per cell (scalar fp16 GEMV) -> memory optimizations changed nothing.
// Fix: tensor-core GEMV. Weights pre-swizzled into mma.m16n8k16 A-fragments
// (fp16); x = [e|h] carried as fp16 hi/lo split in B columns 0/1 (error
// ~2^-22, rel_err unchanged ~8.5e-4). Warp-specialized: h-half mma overlaps
// decode/argmax/e-staging. 192KB asymmetric smem fragment cache.
// ---------------------------------------------------------------------------

#define H    2048
#define BSZ  1024
#define NBK  12

#define NCTA  128
#define NTHR  1024          // 32 warps: (mt = wid>>3) x (ks = wid&7)

// fragment storage: [cta][mt(=gate)][kt(256)][lane(32)] -> uint4 (8 halves)
__device__ uint4 g_wm[(size_t)NCTA * 4 * 256 * 32];   // 67.1 MB
__device__ float g_hbuf[2][H];
__device__ float g_cbuf[H];

#define FLAG_STRIDE 8
__device__ volatile unsigned g_arrive[NCTA * FLAG_STRIDE];

// one-hop barrier; flags zeroed by convert kernel each launch (replay-safe)
__device__ __forceinline__ void grid_sync_flags(unsigned gen) {
    __syncthreads();
    if (threadIdx.x == 0) {
        __threadfence();
        g_arrive[blockIdx.x * FLAG_STRIDE] = gen;
    }
    if (threadIdx.x < NCTA) {
        while (g_arrive[threadIdx.x * FLAG_STRIDE] < gen) { }
    }
    __syncthreads();
}

__device__ __forceinline__ float wred(float v) {
    #pragma unroll
    for (int o = 16; o > 0; o >>= 1) v += __shfl_xor_sync(0xffffffffu, v, o);
    return v;
}

__device__ __forceinline__ float sigf(float x) { return 1.0f / (1.0f + expf(-x)); }

__device__ __forceinline__ unsigned pack2(float a, float b) {
    __half2 h = __floats2half2_rn(a, b);
    return *(unsigned*)&h;
}

__device__ __forceinline__ void mma16816(float* d, uint4 a, uint2 b) {
    asm volatile(
        "mma.sync.aligned.m16n8k16.row.col.f32.f16.f16.f32 "
        "{%0,%1,%2,%3}, {%4,%5,%6,%7}, {%8,%9}, {%0,%1,%2,%3};\n"
        : "+f"(d[0]), "+f"(d[1]), "+f"(d[2]), "+f"(d[3])
        : "r"(a.x), "r"(a.y), "r"(a.z), "r"(a.w), "r"(b.x), "r"(b.y));
}

#define BARB() asm volatile("bar.sync 1, 512;" ::: "memory")   // group B (ks<4)
#define BARA() asm volatile("bar.sync 2, 512;" ::: "memory")   // group A (ks>=4)

// decoder for hidden state produced by cell s
__device__ __forceinline__ void dec_params(int s, const float* dec_act,
                                           const float* dec_block,
                                           const float** dec, int* ncls) {
    if (s == 0) { *dec = dec_act; *ncls = 4; }
    else if (s & 1) { int bid = (s + 1) >> 1; *dec = dec_block + (size_t)(bid - 1) * (NBK - 1) * H; *ncls = bid; }
    else            { int bid = s >> 1;       *dec = dec_act   + (size_t)bid * 4 * H;               *ncls = 4; }
}

// cache geometry: ks<4 (e-half, critical path) cache 16 ktiles; ks>=4 cache 8
__device__ __forceinline__ int cache_off(int mt, int ks) {
    return mt * 96 + ((ks < 4) ? ks * 16 : 64 + (ks - 4) * 8);
}

// ===========================================================================
// Kernel 0: build mma A-fragments. One warp per 16x16 tile.
//   tile T -> cta = T>>10, g = (T>>8)&3, kt = T&255
//   W row = g*2048 + cta*16 + j ; k = kt*16 + .. (k<2048: W_ih, else W_hh)
// Also zeroes barrier flags (replay safety).
// ===========================================================================
__global__ __launch_bounds__(256, 2)
void convert_weights(const float* __restrict__ W_ih, const float* __restrict__ W_hh)
{
    __shared__ unsigned tile[8][16][8];   // per warp: [row][half2 col]

    if (blockIdx.x == 0) {
        for (int i = threadIdx.x; i < NCTA * FLAG_STRIDE; i += 256)
            g_arrive[i] = 0;
    }

    const int wid  = threadIdx.x >> 5;
    const int lane = threadIdx.x & 31;
    const int T    = blockIdx.x * 8 + wid;
    const int kt   = T & 255;
    const int gc   = T >> 8;
    const int g    = gc & 3;
    const int cta  = gc >> 2;
    const int k0   = kt * 16;

    const float* W = (k0 < H) ? W_ih : W_hh;
    const int kk   = k0 & (H - 1);

    const int row  = lane & 15;
    const int half = lane >> 4;
    const size_t rbase = (size_t)(g * H + cta * 16 + row) * H + kk;

    #pragma unroll
    for (int p = 0; p < 2; p++) {
        const int off = half * 4 + p * 8;
        const float4 v = *(const float4*)(W + rbase + off);
        tile[wid][row][(off >> 1) + 0] = pack2(v.x, v.y);
        tile[wid][row][(off >> 1) + 1] = pack2(v.z, v.w);
    }
    __syncwarp();

    const int gr = lane >> 2, c = lane & 3;
    uint4 frag;
    frag.x = tile[wid][gr    ][c    ];
    frag.y = tile[wid][gr + 8][c    ];
    frag.z = tile[wid][gr    ][c + 4];
    frag.w = tile[wid][gr + 8][c + 4];
    g_wm[(size_t)T * 32 + lane] = frag;
}

// ===========================================================================
// Kernel 1: persistent controller, tensor-core GEMV.
// dynamic smem: [0,192K) fragment cache | [192K,200K) h_sm fp32 |
//               [200K,208K) xBhi | [208K,216K) xBlo   (x in B-fragment order)
// xB index: kt*4 + c -> uint2{ half2(x[16kt+2c],x[..+1]), half2(x[16kt+8+2c],..) }
// ===========================================================================
__global__ __launch_bounds__(NTHR, 1)
void controller_main(const float* __restrict__ b_ih,
                     const float* __restrict__ b_hh,
                     const float* __restrict__ enc_act,
                     const float* __restrict__ enc_block,
                     const float* __restrict__ dec_act,
                     const float* __restrict__ dec_block,
                     float* __restrict__ out)
{
    extern __shared__ unsigned char dynsm[];
    uint4* wcache = (uint4*)dynsm;
    float* h_sm   = (float*)(dynsm + 192 * 1024);
    uint2* xBhi   = (uint2*)(dynsm + 200 * 1024);
    uint2* xBlo   = (uint2*)(dynsm + 208 * 1024);

    __shared__ float psum[4][8][16];
    __shared__ float gate_sm[4][16];
    __shared__ float dec_sm[16];
    __shared__ float c_sm[16];
    __shared__ int   idx_sm;

    const int tid  = threadIdx.x;
    const int lane = tid & 31;
    const int wid  = tid >> 5;
    const int mt   = wid >> 3;          // gate 0..3
    const int ks   = wid & 7;           // k-slice
    const bool grpB = (ks < 4);
    const int rb   = mt * 4 + (ks & 3); // rank within group (0..15)
    const int cta  = blockIdx.x;

    // biases for reduce threads (tid<64: g=tid>>4, j=tid&15)
    float bsum = 0.f;
    if (tid < 64) {
        const int g = tid >> 4, j = tid & 15;
        const int r = g * H + cta * 16 + j;
        bsum = b_ih[r] + b_hh[r];
    }

    // fragment pointers
    const uint4* wg  = g_wm + (((size_t)(cta * 4 + mt) * 256 + ks * 32) * 32 + lane);
    const uint4* wcl = wcache + ((size_t)cache_off(mt, ks) * 32 + lane);
    const int nc = grpB ? 16 : 8;       // cached ktiles for this warp

    // ---- fill fragment cache (192 KB) ----
    for (int s = tid; s < 12288; s += NTHR) {
        const int l = s & 31, u = s >> 5;        // u in [0,384)
        const int fmt = u / 96, v = u - fmt * 96;
        int fks, ci;
        if (v < 64) { fks = v >> 4; ci = v & 15; }
        else        { int w2 = v - 64; fks = 4 + (w2 >> 3); ci = w2 & 7; }
        wcache[s] = g_wm[(((size_t)(cta * 4 + fmt) * 256 + fks * 32 + ci) * 32 + l)];
    }
    __syncthreads();

    unsigned gen = 0;

    for (int cell = 0; cell < 2 * NBK - 1; cell++) {
        if (cell == 0) {
            if (tid < 64) gate_sm[tid >> 4][tid & 15] = bsum;
            __syncthreads();
            if (tid < 16) {
                const int j = tid;
                const float c2 = sigf(gate_sm[1][j]) * 0.f + sigf(gate_sm[0][j]) * tanhf(gate_sm[2][j]);
                const float h2 = sigf(gate_sm[3][j]) * tanhf(c2);
                c_sm[j] = c2;
                g_hbuf[0][cta * 16 + j] = h2;
                __threadfence();
            }
        } else {
            const float* hb = g_hbuf[(cell - 1) & 1];

            if (!grpB) {
                // ---- group A: build xB for h-half, then mma kt in [ks*32, ks*32+32) ----
                const int ra   = mt * 4 + (ks - 4);
                const int slot = ra * 32 + lane;          // [0,512)
                const int base = (slot >> 2) * 16 + 2 * (slot & 3);
                const float f0 = __ldcv(hb + base),     f1 = __ldcv(hb + base + 1);
                const float f2 = __ldcv(hb + base + 8), f3 = __ldcv(hb + base + 9);
                const __half h0 = __float2half_rn(f0), h1 = __float2half_rn(f1);
                const __half h2 = __float2half_rn(f2), h3 = __float2half_rn(f3);
                xBhi[512 + slot] = make_uint2(pack2(__half2float(h0), __half2float(h1)) * 0 +
                                              (unsigned)(*(const unsigned short*)&h0 | ((unsigned)*(const unsigned short*)&h1 << 16)),
                                              (unsigned)(*(const unsigned short*)&h2 | ((unsigned)*(const unsigned short*)&h3 << 16)));
                const __half l0 = __float2half_rn(f0 - __half2float(h0));
                const __half l1 = __float2half_rn(f1 - __half2float(h1));
                const __half l2 = __float2half_rn(f2 - __half2float(h2));
                const __half l3 = __float2half_rn(f3 - __half2float(h3));
                xBlo[512 + slot] = make_uint2((unsigned)(*(const unsigned short*)&l0 | ((unsigned)*(const unsigned short*)&l1 << 16)),
                                              (unsigned)(*(const unsigned short*)&l2 | ((unsigned)*(const unsigned short*)&l3 << 16)));
                BARA();
            } else {
                // ---- group B: stage h_sm, decode, argmax, stage e, then mma ----
                {
                    const int i = rb * 32 + lane;         // [0,512) float4
                    ((float4*)h_sm)[i] = __ldcv((const float4*)hb + i);
                }
                BARB();
                const float* dec; int ncls;
                dec_params(cell - 1, dec_act, dec_block, &dec, &ncls);
                if (rb < ncls) {
                    const float4* dr = (const float4*)(dec + (size_t)rb * H);
                    const float4* hp = (const float4*)h_sm;
                    float s = 0.f;
                    #pragma unroll 4
                    for (int t = lane; t < 512; t += 32) {
                        const float4 d = __ldg(dr + t), hv = hp[t];
                        s += d.x*hv.x + d.y*hv.y + d.z*hv.z + d.w*hv.w;
                    }
                    s = wred(s);
                    if (lane == 0) dec_sm[rb] = s;
                }
                BARB();
                float best = dec_sm[0]; int bi = 0;
                for (int j = 1; j < ncls; j++) { float v = dec_sm[j]; if (v > best) { best = v; bi = j; } }
                const int bid = (cell + 1) >> 1;
                const float* emb = (cell & 1)
                    ? enc_act   + ((size_t)(bid - 1) * 4         + bi) * H
                    : enc_block + ((size_t)(bid - 1) * (NBK - 1) + bi) * H;
                {
                    const int slot = rb * 32 + lane;      // [0,512), kt = slot>>2 < 128
                    const int base = (slot >> 2) * 16 + 2 * (slot & 3);
                    const float f0 = __ldg(emb + base),     f1 = __ldg(emb + base + 1);
                    const float f2 = __ldg(emb + base + 8), f3 = __ldg(emb + base + 9);
                    const __half h0 = __float2half_rn(f0), h1 = __float2half_rn(f1);
                    const __half h2 = __float2half_rn(f2), h3 = __float2half_rn(f3);
                    xBhi[slot] = make_uint2((unsigned)(*(const unsigned short*)&h0 | ((unsigned)*(const unsigned short*)&h1 << 16)),
                                            (unsigned)(*(const unsigned short*)&h2 | ((unsigned)*(const unsigned short*)&h3 << 16)));
                    const __half l0 = __float2half_rn(f0 - __half2float(h0));
                    const __half l1 = __float2half_rn(f1 - __half2float(h1));
                    const __half l2 = __float2half_rn(f2 - __half2float(h2));
                    const __half l3 = __float2half_rn(f3 - __half2float(h3));
                    xBlo[slot] = make_uint2((unsigned)(*(const unsigned short*)&l0 | ((unsigned)*(const unsigned short*)&l1 << 16)),
                                            (unsigned)(*(const unsigned short*)&l2 | ((unsigned)*(const unsigned short*)&l3 << 16)));
                }
                BARB();
            }

            // ---- mma: nc cached tiles then 32-nc global tiles ----
            {
                float d0[4] = {0.f, 0.f, 0.f, 0.f};
                float d1[4] = {0.f, 0.f, 0.f, 0.f};
                const int ktbase = ks * 32;
                const bool bl = (lane < 8);
                const uint2* xsrc = (lane < 4) ? xBhi : xBlo;
                const int cb = lane & 3;
                const uint2 bz = make_uint2(0u, 0u);
                #pragma unroll 4
                for (int ci = 0; ci < 16; ci += 2) {
                    if (ci >= nc) break;
                    const uint4 fa = wcl[ci * 32];
                    const uint4 fb = wcl[(ci + 1) * 32];
                    const uint2 ba = bl ? xsrc[(ktbase + ci) * 4 + cb] : bz;
                    const uint2 bbv = bl ? xsrc[(ktbase + ci + 1) * 4 + cb] : bz;
                    mma16816(d0, fa, ba);
                    mma16816(d1, fb, bbv);
                }
                #pragma unroll 4
                for (int kl = nc; kl < 32; kl += 2) {
                    const uint4 fa = wg[kl * 32];
                    const uint4 fb = wg[(kl + 1) * 32];
                    const uint2 ba = bl ? xsrc[(ktbase + kl) * 4 + cb] : bz;
                    const uint2 bbv = bl ? xsrc[(ktbase + kl + 1) * 4 + cb] : bz;
                    mma16816(d0, fa, ba);
                    mma16816(d1, fb, bbv);
                }
                if ((lane & 3) == 0) {
                    const int gr = lane >> 2;
                    psum[mt][ks][gr]     = d0[0] + d0[1] + d1[0] + d1[1];
                    psum[mt][ks][gr + 8] = d0[2] + d0[3] + d1[2] + d1[3];
                }
            }
            __syncthreads();

            // ---- reduce + pointwise ----
            if (tid < 64) {
                const int g = tid >> 4, j = tid & 15;
                float s = bsum;
                #pragma unroll
                for (int k = 0; k < 8; k++) s += psum[g][k][j];
                gate_sm[g][j] = s;
            }
            __syncthreads();
            if (tid < 16) {
                const int j = tid;
                const float gi = gate_sm[0][j], gf = gate_sm[1][j];
                const float gg = gate_sm[2][j], go = gate_sm[3][j];
                const float c2 = sigf(gf) * c_sm[j] + sigf(gi) * tanhf(gg);
                const float h2 = sigf(go) * tanhf(c2);
                c_sm[j] = c2;
                g_hbuf[cell & 1][cta * 16 + j] = h2;
                if (cell == 2 * NBK - 2) g_cbuf[cta * 16 + j] = c2;
                __threadfence();
            }
        }
        gen++;
        grid_sync_flags(gen);
    }

    // ---- epilogue: decode h_22 (buf 0) for the output idx ----
    if (tid < 512)
        ((float4*)h_sm)[tid] = __ldcv((const float4*)g_hbuf[0] + tid);
    __syncthreads();
    {
        const float* dec; int ncls;
        dec_params(2 * NBK - 2, dec_act, dec_block, &dec, &ncls);
        if (wid < ncls) {
            const float4* dr = (const float4*)(dec + (size_t)wid * H);
            const float4* hp = (const float4*)h_sm;
            float s = 0.f;
            #pragma unroll 4
            for (int t = lane; t < 512; t += 32) {
                const float4 d = __ldg(dr + t), hv = hp[t];
                s += d.x*hv.x + d.y*hv.y + d.z*hv.z + d.w*hv.w;
            }
            s = wred(s);
            if (lane == 0) dec_sm[wid] = s;
        }
    }
    __syncthreads();
    if (tid == 0) {
        float best = dec_sm[0]; int bi = 0;
        for (int j = 1; j < 4; j++) { float v = dec_sm[j]; if (v > best) { best = v; bi = j; } }
        idx_sm = bi;
    }
    // stage final c (reuse xB region)
    float4* cst = (float4*)xBhi;
    if (tid < 512) cst[tid] = __ldcv((const float4*)g_cbuf + tid);
    __syncthreads();

    // ---- replicate outputs to all 1024 (identical) batch rows ----
    if (cta == 0) {
        const float idxf = (float)idx_sm;
        for (int i = tid; i < BSZ; i += NTHR) out[i] = idxf;
    }
    float4* outh = (float4*)(out + BSZ);
    float4* outc = (float4*)(out + BSZ + (size_t)BSZ * H);
    const float4* hfin = (const float4*)h_sm;
    for (int r = cta; r < BSZ; r += NCTA) {
        const size_t ro = (size_t)r * 512;
        for (int i = tid; i < 512; i += NTHR) {
            outh[ro + i] = hfin[i];
            outc[ro + i] = cst[i];
        }
    }
}

extern "C" void kernel_launch(void* const* d_in, const int* in_sizes, int n_in,
                              void* d_out, int out_size) {
    // metadata order: inputs, W_ih, W_hh, b_ih, b_hh, enc_act, enc_block, dec_act, dec_block
    const float* W_ih      = (const float*)d_in[1];
    const float* W_hh      = (const float*)d_in[2];
    const float* b_ih      = (const float*)d_in[3];
    const float* b_hh      = (const float*)d_in[4];
    const float* enc_act   = (const float*)d_in[5];
    const float* enc_block = (const float*)d_in[6];
    const float* dec_act   = (const float*)d_in[7];
    const float* dec_block = (const float*)d_in[8];
    float* out = (float*)d_out;

    const int dyn_smem = 216 * 1024;
    cudaFuncSetAttribute(controller_main,
                         cudaFuncAttributeMaxDynamicSharedMemorySize, dyn_smem);

    convert_weights<<<16384, 256>>>(W_ih, W_hh);
    controller_main<<<NCTA, NTHR, dyn_smem>>>(
        b_ih, b_hh, enc_act, enc_block, dec_act, dec_block, out);
}

// round 12
// speedup vs baseline: 1.1351x; 1.1351x over previous
#include <cuda_runtime.h>
#include <cuda_fp16.h>
#include <math.h>

// ---------------------------------------------------------------------------
// ControllerLSTM on GB300, round 10.
// Diagnosis (r9): per-cell critical latency chain (~10us) dominates; compute
// and bandwidth are all <21% utilized. Fix: precompute the entire e-path as a
// table T[112][8192] = E @ W_ih^T with a tensor-core GEMM (~18us, was 128us
// in fp32 SIMT in r2). The persistent loop then only does W_hh*h per cell:
// half the mma, 75% of W_hh in a 192KB smem cache, decode reduced to picking
// a table row (64 scalar loads, overlapped with the h-half mma).
// ---------------------------------------------------------------------------

#define H    2048
#define BSZ  1024
#define NBK  12

#define NCTA  128
#define NTHR  1024          // A warps: wid 0..15 (mma). B warps: wid 16..31.

// W_hh mma A-fragments: [cta*4+g][kt(128)][lane] uint4
__device__ uint4  g_whm[(size_t)NCTA * 4 * 128 * 32];   // 33.5 MB
// gate table: T[row(112)][g*2048 + col]  fp32
__device__ float  g_tab[(size_t)112 * 8192];            // 3.7 MB
// E B-fragments for the table GEMM: [nt(14)][kt(128)][lane] uint2
__device__ uint2  g_eb[(size_t)14 * 128 * 32];          // 459 KB
__device__ float  g_hbuf[2][H];
__device__ float  g_cbuf[H];

#define FLAG_STRIDE 8
__device__ volatile unsigned g_arrive[NCTA * FLAG_STRIDE];

// one-hop barrier; flags zeroed by convert_whh each launch (replay-safe)
__device__ __forceinline__ void grid_sync_flags(unsigned gen) {
    __syncthreads();
    if (threadIdx.x == 0) {
        __threadfence();
        g_arrive[blockIdx.x * FLAG_STRIDE] = gen;
    }
    if (threadIdx.x < NCTA) {
        while (g_arrive[threadIdx.x * FLAG_STRIDE] < gen) { }
    }
    __syncthreads();
}

__device__ __forceinline__ float wred(float v) {
    #pragma unroll
    for (int o = 16; o > 0; o >>= 1) v += __shfl_xor_sync(0xffffffffu, v, o);
    return v;
}

__device__ __forceinline__ float sigf(float x) { return 1.0f / (1.0f + expf(-x)); }

__device__ __forceinline__ unsigned pack2(float a, float b) {
    __half2 h = __floats2half2_rn(a, b);
    return *(unsigned*)&h;
}

__device__ __forceinline__ void split2(float f0, float f1, unsigned& hi, unsigned& lo) {
    const __half h0 = __float2half_rn(f0), h1 = __float2half_rn(f1);
    const __half2 hh = __halves2half2(h0, h1);
    hi = *(const unsigned*)&hh;
    const __half l0 = __float2half_rn(f0 - __half2float(h0));
    const __half l1 = __float2half_rn(f1 - __half2float(h1));
    const __half2 ll = __halves2half2(l0, l1);
    lo = *(const unsigned*)&ll;
}

__device__ __forceinline__ void mma16816(float* d, uint4 a, uint2 b) {
    asm volatile(
        "mma.sync.aligned.m16n8k16.row.col.f32.f16.f16.f32 "
        "{%0,%1,%2,%3}, {%4,%5,%6,%7}, {%8,%9}, {%0,%1,%2,%3};\n"
        : "+f"(d[0]), "+f"(d[1]), "+f"(d[2]), "+f"(d[3])
        : "r"(a.x), "r"(a.y), "r"(a.z), "r"(a.w), "r"(b.x), "r"(b.y));
}

#define BARA() asm volatile("bar.sync 2, 512;" ::: "memory")   // A warps
#define BARB() asm volatile("bar.sync 1, 512;" ::: "memory")   // B warps

// decoder applied to hidden state produced by cell s
__device__ __forceinline__ void dec_params(int s, const float* dec_act,
                                           const float* dec_block,
                                           const float** dec, int* ncls) {
    if (s == 0) { *dec = dec_act; *ncls = 4; }
    else if (s & 1) { int bid = (s + 1) >> 1; *dec = dec_block + (size_t)(bid - 1) * (NBK - 1) * H; *ncls = bid; }
    else            { int bid = s >> 1;       *dec = dec_act   + (size_t)bid * 4 * H;               *ncls = 4; }
}

// table row pointer for embedding row n (0..109; >=110 -> null = zeros)
__device__ __forceinline__ const float* emb_row_ptr(int n, const float* enc_act,
                                                    const float* enc_block) {
    if (n < 44) return enc_act + (size_t)n * H;
    if (n < 110) {
        int r2 = n - 44;
        int bid = 1;
        while (bid * (bid + 1) / 2 <= r2) bid++;
        int j = r2 - bid * (bid - 1) / 2;
        return enc_block + (size_t)((bid - 1) * (NBK - 1) + j) * H;
    }
    return 0;
}

// ===========================================================================
// Kernel 0: W_hh -> mma A-fragments; zero barrier flags.
// ===========================================================================
__global__ __launch_bounds__(256, 2)
void convert_whh(const float* __restrict__ W_hh)
{
    __shared__ unsigned tile[8][16][8];

    if (blockIdx.x == 0) {
        for (int i = threadIdx.x; i < NCTA * FLAG_STRIDE; i += 256)
            g_arrive[i] = 0;
    }

    const int wid  = threadIdx.x >> 5;
    const int lane = threadIdx.x & 31;
    const int T    = blockIdx.x * 8 + wid;        // 65536 tiles
    const int kt   = T & 127;
    const int gc   = T >> 7;                      // cta*4 + g
    const int g    = gc & 3;
    const int cta  = gc >> 2;

    const int row  = lane & 15;
    const int half = lane >> 4;
    const size_t rbase = (size_t)(g * H + cta * 16 + row) * H + kt * 16;

    #pragma unroll
    for (int p = 0; p < 2; p++) {
        const int off = half * 4 + p * 8;
        const float4 v = *(const float4*)(W_hh + rbase + off);
        tile[wid][row][(off >> 1) + 0] = pack2(v.x, v.y);
        tile[wid][row][(off >> 1) + 1] = pack2(v.z, v.w);
    }
    __syncwarp();

    const int gr = lane >> 2, c = lane & 3;
    uint4 frag;
    frag.x = tile[wid][gr    ][c    ];
    frag.y = tile[wid][gr + 8][c    ];
    frag.z = tile[wid][gr    ][c + 4];
    frag.w = tile[wid][gr + 8][c + 4];
    g_whm[(size_t)T * 32 + lane] = frag;
}

// ===========================================================================
// Kernel 1: build E B-fragments (fp16) for the table GEMM.
// ===========================================================================
__global__ __launch_bounds__(256, 4)
void build_eb(const float* __restrict__ enc_act, const float* __restrict__ enc_block)
{
    const int idx = blockIdx.x * 256 + threadIdx.x;      // 14*128*32 = 57344
    if (idx >= 14 * 128 * 32) return;
    const int nt = idx >> 12;
    const int rem = idx & 4095;
    const int kt = rem >> 5;
    const int l  = rem & 31;
    const int n  = nt * 8 + (l >> 2);
    const int k  = kt * 16 + (l & 3) * 2;

    const float* p = emb_row_ptr(n, enc_act, enc_block);
    float f0 = 0.f, f1 = 0.f, f8 = 0.f, f9 = 0.f;
    if (p) { f0 = p[k]; f1 = p[k + 1]; f8 = p[k + 8]; f9 = p[k + 9]; }
    g_eb[idx] = make_uint2(pack2(f0, f1), pack2(f8, f9));
}

// ===========================================================================
// Kernel 2: table GEMM. T[n][m] = sum_k E[n][k] * W_ih[m][k].
// grid 256 CTAs: m-tile of 32 (2 msubs); 8 warps split k (16 ktiles each).
// ===========================================================================
__global__ __launch_bounds__(256, 1)
void table_gemm(const float* __restrict__ W_ih)
{
    extern __shared__ float psum2[];                 // [8][14][16][8] = 57 KB
    __shared__ unsigned tile[8][2][16][8];

    const int tid  = threadIdx.x;
    const int w    = tid >> 5;
    const int lane = tid & 31;
    const int m0   = blockIdx.x * 32;
    const int gr   = lane >> 2, cb = lane & 3;

    float d[2][14][4];
    #pragma unroll
    for (int m = 0; m < 2; m++)
        #pragma unroll
        for (int nt = 0; nt < 14; nt++)
            #pragma unroll
            for (int i = 0; i < 4; i++) d[m][nt][i] = 0.f;

    for (int kt16 = 0; kt16 < 16; kt16++) {
        const int kt = w * 16 + kt16;
        const int row = lane & 15, half = lane >> 4;
        #pragma unroll
        for (int m = 0; m < 2; m++) {
            const size_t rbase = (size_t)(m0 + m * 16 + row) * H + kt * 16;
            #pragma unroll
            for (int p = 0; p < 2; p++) {
                const int off = half * 4 + p * 8;
                const float4 v = *(const float4*)(W_ih + rbase + off);
                tile[w][m][row][(off >> 1) + 0] = pack2(v.x, v.y);
                tile[w][m][row][(off >> 1) + 1] = pack2(v.z, v.w);
            }
        }
        __syncwarp();
        uint4 a0, a1;
        a0.x = tile[w][0][gr][cb];     a0.y = tile[w][0][gr + 8][cb];
        a0.z = tile[w][0][gr][cb + 4]; a0.w = tile[w][0][gr + 8][cb + 4];
        a1.x = tile[w][1][gr][cb];     a1.y = tile[w][1][gr + 8][cb];
        a1.z = tile[w][1][gr][cb + 4]; a1.w = tile[w][1][gr + 8][cb + 4];
        __syncwarp();
        #pragma unroll
        for (int nt = 0; nt < 14; nt++) {
            const uint2 b = g_eb[((size_t)nt * 128 + kt) * 32 + lane];
            mma16816(d[0][nt], a0, b);
            mma16816(d[1][nt], a1, b);
        }
    }

    #pragma unroll
    for (int m = 0; m < 2; m++) {
        #pragma unroll
        for (int nt = 0; nt < 14; nt++) {
            float* p = psum2 + ((size_t)(w * 14 + nt) * 16) * 8;
            p[gr * 8 + 2 * cb]           = d[m][nt][0];
            p[gr * 8 + 2 * cb + 1]       = d[m][nt][1];
            p[(gr + 8) * 8 + 2 * cb]     = d[m][nt][2];
            p[(gr + 8) * 8 + 2 * cb + 1] = d[m][nt][3];
        }
        __syncthreads();
        for (int i = tid; i < 14 * 128; i += 256) {
            const int nt = i >> 7, rem = i & 127;
            const int row = rem >> 3, col = rem & 7;
            float s = 0.f;
            #pragma unroll
            for (int w8 = 0; w8 < 8; w8++)
                s += psum2[(((size_t)(w8 * 14 + nt)) * 16 + row) * 8 + col];
            g_tab[(size_t)(nt * 8 + col) * 8192 + m0 + m * 16 + row] = s;
        }
        __syncthreads();
    }
}

// ===========================================================================
// Kernel 3: persistent controller.
// A warps (wid<16): xB(h) build + W_hh*h mma (75% smem-cached fragments).
// B warps (wid>=16): stage h, decode, argmax, fetch table row.
// dyn smem: [0,192K) wcache | 192K xBhi 4K | 196.5K... xBlo 4K | h_sm 8K.
// ===========================================================================
__global__ __launch_bounds__(NTHR, 1)
void controller_main(const float* __restrict__ b_ih,
                     const float* __restrict__ b_hh,
                     const float* __restrict__ dec_act,
                     const float* __restrict__ dec_block,
                     float* __restrict__ out)
{
    extern __shared__ unsigned char dynsm[];
    uint4* wcache = (uint4*)dynsm;                          // 12288 uint4
    uint2* xBhi   = (uint2*)(dynsm + 196608);               // 512
    uint2* xBlo   = (uint2*)(dynsm + 200704);               // 512
    float* h_smf  = (float*)(dynsm + 204800);               // 2048 fp32

    __shared__ float psum[4][4][16];
    __shared__ float gate_sm[4][16];
    __shared__ float tab_sm[64];
    __shared__ float dec_sm[16];
    __shared__ float c_sm[16];
    __shared__ int   idx_final;

    const int tid  = threadIdx.x;
    const int lane = tid & 31;
    const int wid  = tid >> 5;
    const int cta  = blockIdx.x;

    // biases for reduce threads
    float bsum = 0.f;
    if (tid < 64) {
        const int g = tid >> 4, j = tid & 15;
        const int r = g * H + cta * 16 + j;
        bsum = b_ih[r] + b_hh[r];
    }

    // A-warp geometry
    const int gA  = wid >> 2;          // gate (A warps)
    const int s4  = wid & 3;           // k-slice
    const int ktbase = s4 * 32;
    const uint4* wcl = wcache + (size_t)wid * 24 * 32 + lane;
    const uint4* wgp = g_whm + ((size_t)(cta * 4 + gA) * 128 + ktbase) * 32 + lane;

    // ---- fill 192 KB fragment cache: warp region wid covers ktiles [s4*32, s4*32+24) ----
    for (int s = tid; s < 16 * 24 * 32; s += NTHR) {
        const int l = s & 31, u = s >> 5;
        const int warpi = u / 24, ci = u - warpi * 24;
        const int g = warpi >> 2, sl = warpi & 3;
        wcache[s] = g_whm[((size_t)(cta * 4 + g) * 128 + sl * 32 + ci) * 32 + l];
    }
    __syncthreads();

    unsigned gen = 0;

    for (int cell = 0; cell < 2 * NBK - 1; cell++) {
        if (cell == 0) {
            if (tid < 64) gate_sm[tid >> 4][tid & 15] = bsum;
            __syncthreads();
            if (tid < 16) {
                const int j = tid;
                const float c2 = sigf(gate_sm[0][j]) * tanhf(gate_sm[2][j]);
                const float h2 = sigf(gate_sm[3][j]) * tanhf(c2);
                c_sm[j] = c2;
                g_hbuf[0][cta * 16 + j] = h2;
                __threadfence();
            }
        } else {
            const float* hb = g_hbuf[(cell - 1) & 1];

            if (wid < 16) {
                // ---- A: build xB (hi/lo) then mma ----
                {
                    const int slot = tid;                 // [0,512)
                    const int base = (slot >> 2) * 16 + 2 * (slot & 3);
                    const float2 p0 = __ldcv((const float2*)(hb + base));
                    const float2 p1 = __ldcv((const float2*)(hb + base + 8));
                    unsigned hx, lx, hy, ly;
                    split2(p0.x, p0.y, hx, lx);
                    split2(p1.x, p1.y, hy, ly);
                    xBhi[slot] = make_uint2(hx, hy);
                    xBlo[slot] = make_uint2(lx, ly);
                }
                BARA();
                float d0[4] = {0.f, 0.f, 0.f, 0.f};
                float d1[4] = {0.f, 0.f, 0.f, 0.f};
                const bool bl = (lane < 8);
                const uint2* xsrc = (lane < 4) ? xBhi : xBlo;
                const int cb = lane & 3;
                const uint2 bz = make_uint2(0u, 0u);
                #pragma unroll
                for (int ci = 0; ci < 24; ci += 2) {
                    const uint4 fa = wcl[ci * 32];
                    const uint4 fb = wcl[(ci + 1) * 32];
                    const uint2 ba  = bl ? xsrc[(ktbase + ci) * 4 + cb] : bz;
                    const uint2 bbv = bl ? xsrc[(ktbase + ci + 1) * 4 + cb] : bz;
                    mma16816(d0, fa, ba);
                    mma16816(d1, fb, bbv);
                }
                #pragma unroll
                for (int kl = 24; kl < 32; kl += 2) {
                    const uint4 fa = wgp[kl * 32];
                    const uint4 fb = wgp[(kl + 1) * 32];
                    const uint2 ba  = bl ? xsrc[(ktbase + kl) * 4 + cb] : bz;
                    const uint2 bbv = bl ? xsrc[(ktbase + kl + 1) * 4 + cb] : bz;
                    mma16816(d0, fa, ba);
                    mma16816(d1, fb, bbv);
                }
                if ((lane & 3) == 0) {
                    const int gr = lane >> 2;
                    psum[gA][s4][gr]     = d0[0] + d0[1] + d1[0] + d1[1];
                    psum[gA][s4][gr + 8] = d0[2] + d0[3] + d1[2] + d1[3];
                }
            } else {
                // ---- B: stage h, decode, argmax, table row fetch ----
                const int b = wid - 16;
                {
                    const int i = b * 32 + lane;          // [0,512)
                    ((float4*)h_smf)[i] = __ldcv((const float4*)hb + i);
                }
                BARB();
                const float* dec; int ncls;
                dec_params(cell - 1, dec_act, dec_block, &dec, &ncls);
                if (b < ncls) {
                    const float4* dr = (const float4*)(dec + (size_t)b * H);
                    const float4* hp = (const float4*)h_smf;
                    float s = 0.f;
                    #pragma unroll 4
                    for (int t = lane; t < 512; t += 32) {
                        const float4 dv = __ldg(dr + t), hv = hp[t];
                        s += dv.x*hv.x + dv.y*hv.y + dv.z*hv.z + dv.w*hv.w;
                    }
                    s = wred(s);
                    if (lane == 0) dec_sm[b] = s;
                }
                BARB();
                float best = dec_sm[0]; int bi = 0;
                for (int j = 1; j < ncls; j++) { float v = dec_sm[j]; if (v > best) { best = v; bi = j; } }
                const int bid = (cell + 1) >> 1;
                const int row = (cell & 1) ? ((bid - 1) * 4 + bi)
                                           : (44 + bid * (bid - 1) / 2 + bi);
                if (b < 2) {
                    const int t = b * 32 + lane;
                    if (t < 64)
                        tab_sm[t] = __ldg(g_tab + (size_t)row * 8192 +
                                          (t >> 4) * H + cta * 16 + (t & 15));
                }
            }
            __syncthreads();      // psum + tab_sm ready

            if (tid < 64) {
                const int g = tid >> 4, j = tid & 15;
                float s = bsum + tab_sm[tid];
                #pragma unroll
                for (int k = 0; k < 4; k++) s += psum[g][k][j];
                gate_sm[g][j] = s;
            }
            __syncthreads();
            if (tid < 16) {
                const int j = tid;
                const float gi = gate_sm[0][j], gf = gate_sm[1][j];
                const float gg = gate_sm[2][j], go = gate_sm[3][j];
                const float c2 = sigf(gf) * c_sm[j] + sigf(gi) * tanhf(gg);
                const float h2 = sigf(go) * tanhf(c2);
                c_sm[j] = c2;
                g_hbuf[cell & 1][cta * 16 + j] = h2;
                if (cell == 2 * NBK - 2) g_cbuf[cta * 16 + j] = c2;
                __threadfence();
            }
        }
        gen++;
        grid_sync_flags(gen);
    }

    // ---- epilogue: decode h_22 (buf 0) for the output idx ----
    if (tid < 512)
        ((float4*)h_smf)[tid] = __ldcv((const float4*)g_hbuf[0] + tid);
    __syncthreads();
    {
        const float* dec; int ncls;
        dec_params(2 * NBK - 2, dec_act, dec_block, &dec, &ncls);
        if (wid < ncls) {
            const float4* dr = (const float4*)(dec + (size_t)wid * H);
            const float4* hp = (const float4*)h_smf;
            float s = 0.f;
            #pragma unroll 4
            for (int t = lane; t < 512; t += 32) {
                const float4 dv = __ldg(dr + t), hv = hp[t];
                s += dv.x*hv.x + dv.y*hv.y + dv.z*hv.z + dv.w*hv.w;
            }
            s = wred(s);
            if (lane == 0) dec_sm[wid] = s;
        }
    }
    __syncthreads();
    if (tid == 0) {
        float best = dec_sm[0]; int bi = 0;
        for (int j = 1; j < 4; j++) { float v = dec_sm[j]; if (v > best) { best = v; bi = j; } }
        idx_final = bi;
    }
    // stage final c into the (now free) wcache region
    float4* cst = (float4*)dynsm;
    if (tid < 512) cst[tid] = __ldcv((const float4*)g_cbuf + tid);
    __syncthreads();

    // ---- replicate outputs to all 1024 (identical) batch rows ----
    if (cta == 0) {
        const float idxf = (float)idx_final;
        for (int i = tid; i < BSZ; i += NTHR) out[i] = idxf;
    }
    float4* outh = (float4*)(out + BSZ);
    float4* outc = (float4*)(out + BSZ + (size_t)BSZ * H);
    const float4* hfin = (const float4*)h_smf;
    for (int r = cta; r < BSZ; r += NCTA) {
        const size_t ro = (size_t)r * 512;
        for (int i = tid; i < 512; i += NTHR) {
            outh[ro + i] = hfin[i];
            outc[ro + i] = cst[i];
        }
    }
}

extern "C" void kernel_launch(void* const* d_in, const int* in_sizes, int n_in,
                              void* d_out, int out_size) {
    // metadata order: inputs, W_ih, W_hh, b_ih, b_hh, enc_act, enc_block, dec_act, dec_block
    const float* W_ih      = (const float*)d_in[1];
    const float* W_hh      = (const float*)d_in[2];
    const float* b_ih      = (const float*)d_in[3];
    const float* b_hh      = (const float*)d_in[4];
    const float* enc_act   = (const float*)d_in[5];
    const float* enc_block = (const float*)d_in[6];
    const float* dec_act   = (const float*)d_in[7];
    const float* dec_block = (const float*)d_in[8];
    float* out = (float*)d_out;

    const int main_smem = 212992;   // 192K cache + 4K + 4K + 8K + pad
    cudaFuncSetAttribute(controller_main,
                         cudaFuncAttributeMaxDynamicSharedMemorySize, main_smem);
    const int gemm_smem = 8 * 14 * 16 * 8 * sizeof(float);   // 57344
    cudaFuncSetAttribute(table_gemm,
                         cudaFuncAttributeMaxDynamicSharedMemorySize, gemm_smem);

    convert_whh<<<8192, 256>>>(W_hh);
    build_eb<<<224, 256>>>(enc_act, enc_block);
    table_gemm<<<256, 256, gemm_smem>>>(W_ih);
    controller_main<<<NCTA, NTHR, main_smem>>>(b_ih, b_hh, dec_act, dec_block, out);
}